// round 12
// baseline (speedup 1.0000x reference)
#include <cuda_runtime.h>
#include <cuda_bf16.h>
#include <cuda_fp16.h>
#include <cstdint>

// ---------------- problem constants ----------------
#define NN 2
#define CC 128
#define PP 49
#define OCN 256
#define OO 24
#define NS   (NN*OO*OO*OO)      // 27648 spatial outputs
#define STILES (NS/64)          // 432 spatial tiles of 64

// ---------------- scratch (static, no allocation) ----------------
__device__ __align__(16) float g_t1[(size_t)NN*48*48*PP*CC];      // [n][z48][y48][x49][c]
__device__ __align__(128) __half g_xh[(size_t)NN*PP*PP*PP*CC];    // blurred, fp16
__device__ __align__(128) __half g_w[27*OCN*CC];                  // [tap][oc][c] fp16

// ---------------- PTX helpers (portable: sm_80+ features only) ----------------
__device__ __forceinline__ uint32_t smem_u32(const void* p) {
    uint32_t a;
    asm("{ .reg .u64 t; cvta.to.shared.u64 t, %1; cvt.u32.u64 %0, t; }" : "=r"(a) : "l"(p));
    return a;
}
__device__ __forceinline__ void cp_async16(uint32_t saddr, const void* gaddr) {
    asm volatile("cp.async.cg.shared.global [%0], [%1], 16;" :: "r"(saddr), "l"(gaddr) : "memory");
}
__device__ __forceinline__ void cp_commit() { asm volatile("cp.async.commit_group;" ::: "memory"); }

__device__ __forceinline__ void ldsm_x4(uint32_t* r, uint32_t addr) {
    asm volatile("ldmatrix.sync.aligned.m8n8.x4.shared.b16 {%0,%1,%2,%3}, [%4];"
        : "=r"(r[0]), "=r"(r[1]), "=r"(r[2]), "=r"(r[3]) : "r"(addr));
}
__device__ __forceinline__ void mma16816(float* d, const uint32_t* a, const uint32_t* b) {
    asm volatile("mma.sync.aligned.m16n8k16.row.col.f32.f16.f16.f32 "
        "{%0,%1,%2,%3}, {%4,%5,%6,%7}, {%8,%9}, {%0,%1,%2,%3};"
        : "+f"(d[0]), "+f"(d[1]), "+f"(d[2]), "+f"(d[3])
        : "r"(a[0]), "r"(a[1]), "r"(a[2]), "r"(a[3]), "r"(b[0]), "r"(b[1]));
}

// SW128 swizzled byte address of the 16B chunk (row, kb) in a row x 128B tile
__device__ __forceinline__ uint32_t sw_addr(uint32_t base, int row, int kb) {
    return base + row * 128 + ((kb ^ (row & 7)) * 16);
}

// ---------------- weight prep: w[oc][c][tap] fp32 -> g_w [tap][oc][c] fp16 ----------------
__global__ void wprep(const float* __restrict__ w) {
    int idx = blockIdx.x * 256 + threadIdx.x;
    if (idx >= OCN * CC * 27) return;
    int oc = idx / (CC * 27);
    int r = idx % (CC * 27);
    int c = r / 27, tap = r % 27;
    g_w[(tap * OCN + oc) * CC + c] = __float2half(w[idx]);
}

// ---------------- blur X + transpose to channel-last ----------------
// x[n][c][z][y][x48] -> t1[n][z][y][x49][c]
__global__ __launch_bounds__(128) void blurX(const float* __restrict__ x) {
    __shared__ float s[128 * 49];   // [c][x] rows padded to 49 (conflict-free)
    int bx = blockIdx.x;            // z*48 + y
    int n = blockIdx.y;
    int z = bx / 48, y = bx % 48;
    int tid = threadIdx.x;
    const float* base = x + (size_t)n * CC * 110592 + (size_t)(z * 48 + y) * 48;
    for (int i = tid; i < 128 * 12; i += 128) {
        int c = i / 12, v = i % 12;
        float4 d = *(const float4*)(base + (size_t)c * 110592 + v * 4);
        float* sr = s + c * 49 + v * 4;
        sr[0] = d.x; sr[1] = d.y; sr[2] = d.z; sr[3] = d.w;
    }
    __syncthreads();
    const float k0 = 1.f / 11.f, k1 = 3.f / 11.f;
    float* dst = g_t1 + ((size_t)((n * 48 + z) * 48 + y)) * 49 * 128;
    const float* sc = s + tid * 49;
    for (int xo = 0; xo < 49; xo++) {
        float v = 0.f;
        #pragma unroll
        for (int e = 0; e < 5; e++) {
            int xi = xo + e - 3;
            float k = (e == 0 || e == 4) ? k0 : k1;
            if (xi >= 0 && xi < 48) v += k * sc[xi];
        }
        dst[xo * 128 + tid] = v;
    }
}

// ---------------- fused blur Y+Z, fp16 out ----------------
// t1[n][z48][y48][xc] -> g_xh[n][z49][y49][xc], xc = x49*c128/4 = 1568 float4 lanes.
// Thread: fixed (n, yo, xc); streams z with a 5-deep register ring of y-blurred rows.
__global__ __launch_bounds__(256) void blurYZ() {
    int idx = blockIdx.x * 256 + threadIdx.x;
    const int total = NN * PP * 1568;      // (n, yo, xc)
    if (idx >= total) return;
    int xc = idx % 1568;
    int t = idx / 1568;
    int yo = t % PP;
    int n = t / PP;
    const float k0 = 1.f / 11.f, k1 = 3.f / 11.f;

    // valid y taps for this yo
    int yis[5]; float wy[5]; int nty = 0;
    #pragma unroll
    for (int e = 0; e < 5; e++) {
        int yi = yo + e - 3;
        if (yi >= 0 && yi < 48) { yis[nty] = yi; wy[nty] = (e == 0 || e == 4) ? k0 : k1; nty++; }
    }

    const float4* t1b = (const float4*)g_t1 + (size_t)n * 48 * 48 * 1568 + xc;
    uint2* dst = (uint2*)g_xh + ((size_t)n * PP * PP + yo) * 1568 + xc;   // +zo*PP*1568 per slice

    float4 r0, r1, r2, r3, r4;
    r0 = r1 = r2 = r3 = r4 = make_float4(0.f, 0.f, 0.f, 0.f);

    for (int zi = 0; zi < 50; zi++) {
        float4 ty = make_float4(0.f, 0.f, 0.f, 0.f);
        if (zi < 48) {
            for (int q = 0; q < nty; q++) {
                float4 d = t1b[(size_t)(zi * 48 + yis[q]) * 1568];
                float k = wy[q];
                ty.x += k * d.x; ty.y += k * d.y; ty.z += k * d.z; ty.w += k * d.w;
            }
        }
        r0 = r1; r1 = r2; r2 = r3; r3 = r4; r4 = ty;
        int zo = zi - 1;
        if (zo >= 0) {
            float4 o;
            o.x = k0 * (r0.x + r4.x) + k1 * (r1.x + r2.x + r3.x);
            o.y = k0 * (r0.y + r4.y) + k1 * (r1.y + r2.y + r3.y);
            o.z = k0 * (r0.z + r4.z) + k1 * (r1.z + r2.z + r3.z);
            o.w = k0 * (r0.w + r4.w) + k1 * (r1.w + r2.w + r3.w);
            __half h0 = __float2half(o.x), h1 = __float2half(o.y);
            __half h2 = __float2half(o.z), h3 = __float2half(o.w);
            uint2 pk;
            pk.x = (uint32_t)__half_as_ushort(h0) | ((uint32_t)__half_as_ushort(h1) << 16);
            pk.y = (uint32_t)__half_as_ushort(h2) | ((uint32_t)__half_as_ushort(h3) << 16);
            dst[(size_t)zo * PP * 1568] = pk;
        }
    }
}

// ---------------- GEMM via mma.sync fp16 (HMMA.16816), single term ----------------
// CTA: 128 oc x 64 spatial. 8 warps: 4M x 2N, warp tile 32 x 32, acc 32 regs.
// 54 stages = 27 taps x 2 channel-halves (K=64). Stage = W 16KB + X 8KB = 24KB;
// 3 buffers = 72KB; cp.async depth-2 pipeline; 3 CTAs/SM (444 slots, grid 864).
__global__ __launch_bounds__(256, 3) void gemm_k(const float* __restrict__ bias,
                                                 float* __restrict__ out) {
    extern __shared__ char smem[];
    __shared__ int s_soff[64];
    uint32_t sb = smem_u32(smem);
    int tid = threadIdx.x, wid = tid >> 5, lane = tid & 31;
    int stile = blockIdx.x, ocg = blockIdx.y;
    int wm = (wid & 3) * 32;      // M (oc) offset in CTA tile
    int wn = (wid >> 2) * 32;     // N (spatial) offset

    // spatial base offsets (in 256B rows of channel-last layout) — computed once
    if (tid < 64) {
        int s = stile * 64 + tid;
        int n = s / 13824; int r = s % 13824;
        int oz = r / 576, r2 = r % 576, oy = r2 / 24, ox = r2 % 24;
        s_soff[tid] = ((n * 49 + 2 * oz) * 49 + 2 * oy) * 49 + 2 * ox;
    }
    __syncthreads();

    // issue cp.async for one stage (tap, half) into buffer b
    auto load_stage = [&](int st, int b) {
        int tap = st >> 1, half = st & 1;
        int dz = tap / 9, dy = (tap / 3) % 3, dx = tap % 3;
        int dtap = dz * 2401 + dy * 49 + dx;
        uint32_t bufbase = sb + b * 24576;
        size_t adelta = (size_t)tap * 65536 + half * 128;       // bytes into g_w
        size_t bdelta = (size_t)dtap * 256 + half * 128;        // bytes into g_xh
        #pragma unroll
        for (int it = 0; it < 6; it++) {
            int i = tid + it * 256;
            int v = i & 7;
            const char* g;
            uint32_t daddr;
            if (i < 1024) {           // W tile: 128 rows x 128B
                int row = (i >> 3) & 127;
                g = (const char*)g_w + adelta + (size_t)(ocg * 128 + row) * 256 + v * 16;
                daddr = bufbase + (uint32_t)(row * 128 + ((v ^ (row & 7)) * 16));
            } else {                  // X tile: 64 rows x 128B
                int row = (i >> 3) - 128;
                g = (const char*)g_xh + bdelta + (size_t)s_soff[row] * 256 + v * 16;
                daddr = bufbase + 16384 + (uint32_t)(row * 128 + ((v ^ (row & 7)) * 16));
            }
            cp_async16(daddr, g);
        }
        cp_commit();
    };

    float acc[2][4][4];
    #pragma unroll
    for (int i = 0; i < 2; i++)
        #pragma unroll
        for (int j = 0; j < 4; j++)
            #pragma unroll
            for (int q = 0; q < 4; q++) acc[i][j][q] = 0.f;

    load_stage(0, 0);
    load_stage(1, 1);

    for (int st = 0; st < 54; st++) {
        int b = st % 3;
        if (st >= 52) asm volatile("cp.async.wait_group 0;" ::: "memory");
        else          asm volatile("cp.async.wait_group 1;" ::: "memory");
        __syncthreads();   // all warps done with stage st-1 -> safe to refill its buffer
        if (st + 2 < 54) load_stage(st + 2, (st + 2) % 3);

        uint32_t bufbase = sb + b * 24576;
        uint32_t tW = bufbase, tX = bufbase + 16384;

        #pragma unroll
        for (int ks = 0; ks < 4; ks++) {
            uint32_t aw[2][4];
            int arow = wm + (lane & 15);
            int akb = ks * 2 + (lane >> 4);
            #pragma unroll
            for (int i = 0; i < 2; i++)
                ldsm_x4(aw[i], sw_addr(tW, arow + i * 16, akb));
            int brow0 = wn + (lane & 7) + ((lane >> 4) << 3);
            int bkb = ks * 2 + ((lane >> 3) & 1);
            #pragma unroll
            for (int j2 = 0; j2 < 2; j2++) {
                uint32_t bh[4];
                ldsm_x4(bh, sw_addr(tX, brow0 + j2 * 16, bkb));
                #pragma unroll
                for (int i = 0; i < 2; i++) {
                    mma16816(acc[i][2 * j2],     aw[i], bh);      // n-lo
                    mma16816(acc[i][2 * j2 + 1], aw[i], bh + 2);  // n-hi
                }
            }
        }
    }

    // ---- epilogue: + bias, direct stores (pairs of consecutive spatial) ----
    #pragma unroll
    for (int i = 0; i < 2; i++) {
        int ocb = ocg * 128 + wm + i * 16 + (lane >> 2);
        float bv0 = bias[ocb], bv1 = bias[ocb + 8];
        #pragma unroll
        for (int j = 0; j < 4; j++) {
            int col = wn + j * 8 + (lane & 3) * 2;
            int s = stile * 64 + col;
            int nb = s / 13824, r2 = s % 13824;
            float2 v0 = make_float2(acc[i][j][0] + bv0, acc[i][j][1] + bv0);
            float2 v1 = make_float2(acc[i][j][2] + bv1, acc[i][j][3] + bv1);
            *(float2*)(out + ((size_t)(nb * OCN + ocb) * 13824 + r2)) = v0;
            *(float2*)(out + ((size_t)(nb * OCN + ocb + 8) * 13824 + r2)) = v1;
        }
    }
}

// ---------------- launch ----------------
extern "C" void kernel_launch(void* const* d_in, const int* in_sizes, int n_in,
                              void* d_out, int out_size) {
    const float* x    = (const float*)d_in[0];   // (2,128,48,48,48)
    const float* wgt  = (const float*)d_in[1];   // (256,128,3,3,3)
    const float* bias = (const float*)d_in[2];   // (256,)
    float* out = (float*)d_out;                  // (2,256,24,24,24)

    {
        int total = OCN * CC * 27;
        wprep<<<(total + 255) / 256, 256>>>(wgt);
    }
    {
        dim3 grid(48 * 48, NN);
        blurX<<<grid, 128>>>(x);
    }
    {
        int total = NN * PP * 1568;
        blurYZ<<<(total + 255) / 256, 256>>>();
    }
    {
        static int smem_set = 0;
        const int smem_bytes = 3 * 24576;   // 73728
        if (!smem_set) {
            cudaFuncSetAttribute(gemm_k, cudaFuncAttributeMaxDynamicSharedMemorySize, smem_bytes);
            smem_set = 1;
        }
        dim3 grid(STILES, 2);
        gemm_k<<<grid, 256, smem_bytes>>>(bias, out);
    }
}

// round 15
// speedup vs baseline: 1.0463x; 1.0463x over previous
#include <cuda_runtime.h>
#include <cuda_bf16.h>
#include <cuda_fp16.h>
#include <cstdint>

// ---------------- problem constants ----------------
#define NN 2
#define CC 128
#define PP 49
#define OCN 256
#define OO 24
#define NS   (NN*OO*OO*OO)      // 27648 spatial outputs
#define STILES (NS/64)          // 432 spatial tiles of 64

// ---------------- scratch (static, no allocation) ----------------
__device__ __align__(16) float g_t1[(size_t)NN*48*48*PP*CC];      // [n][z48][y48][x49][c]
__device__ __align__(128) __half g_xh[(size_t)NN*PP*PP*PP*CC];    // blurred, fp16
__device__ __align__(128) __half g_w[27*OCN*CC];                  // [tap][oc][c] fp16

// ---------------- PTX helpers (portable: sm_80+ features only) ----------------
__device__ __forceinline__ uint32_t smem_u32(const void* p) {
    uint32_t a;
    asm("{ .reg .u64 t; cvta.to.shared.u64 t, %1; cvt.u32.u64 %0, t; }" : "=r"(a) : "l"(p));
    return a;
}
__device__ __forceinline__ void cp_async16(uint32_t saddr, const void* gaddr) {
    asm volatile("cp.async.cg.shared.global [%0], [%1], 16;" :: "r"(saddr), "l"(gaddr) : "memory");
}
__device__ __forceinline__ void cp_commit() { asm volatile("cp.async.commit_group;" ::: "memory"); }

__device__ __forceinline__ void ldsm_x4(uint32_t* r, uint32_t addr) {
    asm volatile("ldmatrix.sync.aligned.m8n8.x4.shared.b16 {%0,%1,%2,%3}, [%4];"
        : "=r"(r[0]), "=r"(r[1]), "=r"(r[2]), "=r"(r[3]) : "r"(addr));
}
__device__ __forceinline__ void mma16816(float* d, const uint32_t* a, const uint32_t* b) {
    asm volatile("mma.sync.aligned.m16n8k16.row.col.f32.f16.f16.f32 "
        "{%0,%1,%2,%3}, {%4,%5,%6,%7}, {%8,%9}, {%0,%1,%2,%3};"
        : "+f"(d[0]), "+f"(d[1]), "+f"(d[2]), "+f"(d[3])
        : "r"(a[0]), "r"(a[1]), "r"(a[2]), "r"(a[3]), "r"(b[0]), "r"(b[1]));
}

// SW128 swizzled byte address of the 16B chunk (row, kb) in a row x 128B tile
__device__ __forceinline__ uint32_t sw_addr(uint32_t base, int row, int kb) {
    return base + row * 128 + ((kb ^ (row & 7)) * 16);
}

// ---------------- weight prep: w[oc][c][tap] fp32 -> g_w [tap][oc][c] fp16 ----------------
__global__ void wprep(const float* __restrict__ w) {
    int idx = blockIdx.x * 256 + threadIdx.x;
    if (idx >= OCN * CC * 27) return;
    int oc = idx / (CC * 27);
    int r = idx % (CC * 27);
    int c = r / 27, tap = r % 27;
    g_w[(tap * OCN + oc) * CC + c] = __float2half(w[idx]);
}

// ---------------- blur X + transpose to channel-last ----------------
// x[n][c][z][y][x48] -> t1[n][z][y][x49][c]
__global__ __launch_bounds__(128) void blurX(const float* __restrict__ x) {
    __shared__ float s[128 * 49];   // [c][x] rows padded to 49 (conflict-free)
    int bx = blockIdx.x;            // z*48 + y
    int n = blockIdx.y;
    int z = bx / 48, y = bx % 48;
    int tid = threadIdx.x;
    const float* base = x + (size_t)n * CC * 110592 + (size_t)(z * 48 + y) * 48;
    for (int i = tid; i < 128 * 12; i += 128) {
        int c = i / 12, v = i % 12;
        float4 d = *(const float4*)(base + (size_t)c * 110592 + v * 4);
        float* sr = s + c * 49 + v * 4;
        sr[0] = d.x; sr[1] = d.y; sr[2] = d.z; sr[3] = d.w;
    }
    __syncthreads();
    const float k0 = 1.f / 11.f, k1 = 3.f / 11.f;
    float* dst = g_t1 + ((size_t)((n * 48 + z) * 48 + y)) * 49 * 128;
    const float* sc = s + tid * 49;
    for (int xo = 0; xo < 49; xo++) {
        float v = 0.f;
        #pragma unroll
        for (int e = 0; e < 5; e++) {
            int xi = xo + e - 3;
            float k = (e == 0 || e == 4) ? k0 : k1;
            if (xi >= 0 && xi < 48) v += k * sc[xi];
        }
        dst[xo * 128 + tid] = v;
    }
}

// ---------------- fused blur Y+Z, fp16 out ----------------
// t1[n][z48][y48][xc] -> g_xh[n][z49][y49][xc], xc = x49*c128/4 = 1568 float4 lanes.
// Thread: fixed (n, yo, xc); streams z with a 5-deep register ring of y-blurred rows.
__global__ __launch_bounds__(256) void blurYZ() {
    int idx = blockIdx.x * 256 + threadIdx.x;
    const int total = NN * PP * 1568;      // (n, yo, xc)
    if (idx >= total) return;
    int xc = idx % 1568;
    int t = idx / 1568;
    int yo = t % PP;
    int n = t / PP;
    const float k0 = 1.f / 11.f, k1 = 3.f / 11.f;

    // valid y taps for this yo
    int yis[5]; float wy[5]; int nty = 0;
    #pragma unroll
    for (int e = 0; e < 5; e++) {
        int yi = yo + e - 3;
        if (yi >= 0 && yi < 48) { yis[nty] = yi; wy[nty] = (e == 0 || e == 4) ? k0 : k1; nty++; }
    }

    const float4* t1b = (const float4*)g_t1 + (size_t)n * 48 * 48 * 1568 + xc;
    uint2* dst = (uint2*)g_xh + ((size_t)n * PP * PP + yo) * 1568 + xc;   // +zo*PP*1568 per slice

    float4 r0, r1, r2, r3, r4;
    r0 = r1 = r2 = r3 = r4 = make_float4(0.f, 0.f, 0.f, 0.f);

    for (int zi = 0; zi < 50; zi++) {
        float4 ty = make_float4(0.f, 0.f, 0.f, 0.f);
        if (zi < 48) {
            for (int q = 0; q < nty; q++) {
                float4 d = t1b[(size_t)(zi * 48 + yis[q]) * 1568];
                float k = wy[q];
                ty.x += k * d.x; ty.y += k * d.y; ty.z += k * d.z; ty.w += k * d.w;
            }
        }
        r0 = r1; r1 = r2; r2 = r3; r3 = r4; r4 = ty;
        int zo = zi - 1;
        if (zo >= 0) {
            float4 o;
            o.x = k0 * (r0.x + r4.x) + k1 * (r1.x + r2.x + r3.x);
            o.y = k0 * (r0.y + r4.y) + k1 * (r1.y + r2.y + r3.y);
            o.z = k0 * (r0.z + r4.z) + k1 * (r1.z + r2.z + r3.z);
            o.w = k0 * (r0.w + r4.w) + k1 * (r1.w + r2.w + r3.w);
            __half h0 = __float2half(o.x), h1 = __float2half(o.y);
            __half h2 = __float2half(o.z), h3 = __float2half(o.w);
            uint2 pk;
            pk.x = (uint32_t)__half_as_ushort(h0) | ((uint32_t)__half_as_ushort(h1) << 16);
            pk.y = (uint32_t)__half_as_ushort(h2) | ((uint32_t)__half_as_ushort(h3) << 16);
            dst[(size_t)zo * PP * 1568] = pk;
        }
    }
}

// ---------------- GEMM via mma.sync fp16 (HMMA.16816), single term ----------------
// CTA: 128 oc x 64 spatial, 4 warps (2M x 2N), warp tile 64 x 32 (same as the
// best R10 config — preserved per-warp LDSM:HMMA efficiency).
// 54 stages = 27 taps x 2 channel-halves (K=64). Stage = W 16KB + X 8KB = 24KB;
// 3 buffers = 72KB; cp.async depth-2 pipeline; 3 CTAs/SM -> 444 slots, grid 864.
__global__ __launch_bounds__(128, 3) void gemm_k(const float* __restrict__ bias,
                                                 float* __restrict__ out) {
    extern __shared__ char smem[];
    __shared__ int s_soff[64];
    uint32_t sb = smem_u32(smem);
    int tid = threadIdx.x, wid = tid >> 5, lane = tid & 31;
    int stile = blockIdx.x, ocg = blockIdx.y;
    int wm = (wid & 1) * 64;      // M (oc) offset in CTA tile
    int wn = (wid >> 1) * 32;     // N (spatial) offset

    // spatial base offsets (in 256B rows of channel-last layout) — computed once
    if (tid < 64) {
        int s = stile * 64 + tid;
        int n = s / 13824; int r = s % 13824;
        int oz = r / 576, r2 = r % 576, oy = r2 / 24, ox = r2 % 24;
        s_soff[tid] = ((n * 49 + 2 * oz) * 49 + 2 * oy) * 49 + 2 * ox;
    }
    __syncthreads();

    // issue cp.async for one stage (tap, half) into buffer b
    auto load_stage = [&](int st, int b) {
        int tap = st >> 1, half = st & 1;
        int dz = tap / 9, dy = (tap / 3) % 3, dx = tap % 3;
        int dtap = dz * 2401 + dy * 49 + dx;
        uint32_t bufbase = sb + b * 24576;
        size_t adelta = (size_t)tap * 65536 + half * 128;       // bytes into g_w
        size_t bdelta = (size_t)dtap * 256 + half * 128;        // bytes into g_xh
        #pragma unroll
        for (int it = 0; it < 12; it++) {
            int i = tid + it * 128;
            int v = i & 7;
            const char* g;
            uint32_t daddr;
            if (i < 1024) {           // W tile: 128 rows x 128B
                int row = i >> 3;
                g = (const char*)g_w + adelta + (size_t)(ocg * 128 + row) * 256 + v * 16;
                daddr = bufbase + (uint32_t)(row * 128 + ((v ^ (row & 7)) * 16));
            } else {                  // X tile: 64 rows x 128B
                int row = (i >> 3) - 128;
                g = (const char*)g_xh + bdelta + (size_t)s_soff[row] * 256 + v * 16;
                daddr = bufbase + 16384 + (uint32_t)(row * 128 + ((v ^ (row & 7)) * 16));
            }
            cp_async16(daddr, g);
        }
        cp_commit();
    };

    float acc[4][4][4];
    #pragma unroll
    for (int i = 0; i < 4; i++)
        #pragma unroll
        for (int j = 0; j < 4; j++)
            #pragma unroll
            for (int q = 0; q < 4; q++) acc[i][j][q] = 0.f;

    load_stage(0, 0);
    load_stage(1, 1);

    for (int st = 0; st < 54; st++) {
        int b = st % 3;
        if (st >= 52) asm volatile("cp.async.wait_group 0;" ::: "memory");
        else          asm volatile("cp.async.wait_group 1;" ::: "memory");
        __syncthreads();   // all warps done with stage st-1 -> safe to refill its buffer
        if (st + 2 < 54) load_stage(st + 2, (st + 2) % 3);

        uint32_t bufbase = sb + b * 24576;
        uint32_t tW = bufbase, tX = bufbase + 16384;

        #pragma unroll
        for (int ks = 0; ks < 4; ks++) {
            uint32_t aw[4][4];
            int arow = wm + (lane & 15);
            int akb = ks * 2 + (lane >> 4);
            #pragma unroll
            for (int i = 0; i < 4; i++)
                ldsm_x4(aw[i], sw_addr(tW, arow + i * 16, akb));
            int brow0 = wn + (lane & 7) + ((lane >> 4) << 3);
            int bkb = ks * 2 + ((lane >> 3) & 1);
            #pragma unroll
            for (int j2 = 0; j2 < 2; j2++) {
                uint32_t bh[4];
                ldsm_x4(bh, sw_addr(tX, brow0 + j2 * 16, bkb));
                #pragma unroll
                for (int i = 0; i < 4; i++) {
                    mma16816(acc[i][2 * j2],     aw[i], bh);      // n-lo
                    mma16816(acc[i][2 * j2 + 1], aw[i], bh + 2);  // n-hi
                }
            }
        }
    }

    // ---- epilogue: + bias, direct stores (pairs of consecutive spatial) ----
    #pragma unroll
    for (int i = 0; i < 4; i++) {
        int ocb = ocg * 128 + wm + i * 16 + (lane >> 2);
        float bv0 = bias[ocb], bv1 = bias[ocb + 8];
        #pragma unroll
        for (int j = 0; j < 4; j++) {
            int col = wn + j * 8 + (lane & 3) * 2;
            int s = stile * 64 + col;
            int nb = s / 13824, r2 = s % 13824;
            float2 v0 = make_float2(acc[i][j][0] + bv0, acc[i][j][1] + bv0);
            float2 v1 = make_float2(acc[i][j][2] + bv1, acc[i][j][3] + bv1);
            *(float2*)(out + ((size_t)(nb * OCN + ocb) * 13824 + r2)) = v0;
            *(float2*)(out + ((size_t)(nb * OCN + ocb + 8) * 13824 + r2)) = v1;
        }
    }
}

// ---------------- launch ----------------
extern "C" void kernel_launch(void* const* d_in, const int* in_sizes, int n_in,
                              void* d_out, int out_size) {
    const float* x    = (const float*)d_in[0];   // (2,128,48,48,48)
    const float* wgt  = (const float*)d_in[1];   // (256,128,3,3,3)
    const float* bias = (const float*)d_in[2];   // (256,)
    float* out = (float*)d_out;                  // (2,256,24,24,24)

    {
        int total = OCN * CC * 27;
        wprep<<<(total + 255) / 256, 256>>>(wgt);
    }
    {
        dim3 grid(48 * 48, NN);
        blurX<<<grid, 128>>>(x);
    }
    {
        int total = NN * PP * 1568;
        blurYZ<<<(total + 255) / 256, 256>>>();
    }
    {
        static int smem_set = 0;
        const int smem_bytes = 3 * 24576;   // 73728
        if (!smem_set) {
            cudaFuncSetAttribute(gemm_k, cudaFuncAttributeMaxDynamicSharedMemorySize, smem_bytes);
            smem_set = 1;
        }
        dim3 grid(STILES, 2);
        gemm_k<<<grid, 128, smem_bytes>>>(bias, out);
    }
}

// round 16
// speedup vs baseline: 1.0663x; 1.0191x over previous
#include <cuda_runtime.h>
#include <cuda_bf16.h>
#include <cuda_fp16.h>
#include <cstdint>

// ---------------- problem constants ----------------
#define NN 2
#define CC 128
#define PP 49
#define OCN 256
#define OO 24
#define NS   (NN*OO*OO*OO)      // 27648 spatial outputs
#define STILES (NS/64)          // 432 spatial tiles of 64

// ---------------- scratch (static, no allocation) ----------------
__device__ __align__(16) float g_t1[(size_t)NN*48*48*PP*CC];      // [n][z48][y48][x49][c]
__device__ __align__(128) __half g_xh[(size_t)NN*PP*PP*PP*CC];    // blurred, fp16
__device__ __align__(128) __half g_w[27*OCN*CC];                  // [tap][oc][c] fp16

// ---------------- PTX helpers (portable: sm_80+ features only) ----------------
__device__ __forceinline__ uint32_t smem_u32(const void* p) {
    uint32_t a;
    asm("{ .reg .u64 t; cvta.to.shared.u64 t, %1; cvt.u32.u64 %0, t; }" : "=r"(a) : "l"(p));
    return a;
}
__device__ __forceinline__ void cp_async16(uint32_t saddr, const void* gaddr) {
    asm volatile("cp.async.cg.shared.global [%0], [%1], 16;" :: "r"(saddr), "l"(gaddr) : "memory");
}
__device__ __forceinline__ void cp_commit() { asm volatile("cp.async.commit_group;" ::: "memory"); }

__device__ __forceinline__ void ldsm_x4(uint32_t* r, uint32_t addr) {
    asm volatile("ldmatrix.sync.aligned.m8n8.x4.shared.b16 {%0,%1,%2,%3}, [%4];"
        : "=r"(r[0]), "=r"(r[1]), "=r"(r[2]), "=r"(r[3]) : "r"(addr));
}
__device__ __forceinline__ void mma16816(float* d, const uint32_t* a, const uint32_t* b) {
    asm volatile("mma.sync.aligned.m16n8k16.row.col.f32.f16.f16.f32 "
        "{%0,%1,%2,%3}, {%4,%5,%6,%7}, {%8,%9}, {%0,%1,%2,%3};"
        : "+f"(d[0]), "+f"(d[1]), "+f"(d[2]), "+f"(d[3])
        : "r"(a[0]), "r"(a[1]), "r"(a[2]), "r"(a[3]), "r"(b[0]), "r"(b[1]));
}

// SW128 swizzled byte address of the 16B chunk (row, kb) in a row x 128B tile
__device__ __forceinline__ uint32_t sw_addr(uint32_t base, int row, int kb) {
    return base + row * 128 + ((kb ^ (row & 7)) * 16);
}

// ---------------- weight prep: w[oc][c][tap] fp32 -> g_w [tap][oc][c] fp16 ----------------
__global__ void wprep(const float* __restrict__ w) {
    int idx = blockIdx.x * 256 + threadIdx.x;
    if (idx >= OCN * CC * 27) return;
    int oc = idx / (CC * 27);
    int r = idx % (CC * 27);
    int c = r / 27, tap = r % 27;
    g_w[(tap * OCN + oc) * CC + c] = __float2half(w[idx]);
}

// ---------------- blur X + transpose to channel-last ----------------
// x[n][c][z][y][x48] -> t1[n][z][y][x49][c]
__global__ __launch_bounds__(128) void blurX(const float* __restrict__ x) {
    __shared__ float s[128 * 49];   // [c][x] rows padded to 49 (conflict-free)
    int bx = blockIdx.x;            // z*48 + y
    int n = blockIdx.y;
    int z = bx / 48, y = bx % 48;
    int tid = threadIdx.x;
    const float* base = x + (size_t)n * CC * 110592 + (size_t)(z * 48 + y) * 48;
    for (int i = tid; i < 128 * 12; i += 128) {
        int c = i / 12, v = i % 12;
        float4 d = *(const float4*)(base + (size_t)c * 110592 + v * 4);
        float* sr = s + c * 49 + v * 4;
        sr[0] = d.x; sr[1] = d.y; sr[2] = d.z; sr[3] = d.w;
    }
    __syncthreads();
    const float k0 = 1.f / 11.f, k1 = 3.f / 11.f;
    float* dst = g_t1 + ((size_t)((n * 48 + z) * 48 + y)) * 49 * 128;
    const float* sc = s + tid * 49;
    for (int xo = 0; xo < 49; xo++) {
        float v = 0.f;
        #pragma unroll
        for (int e = 0; e < 5; e++) {
            int xi = xo + e - 3;
            float k = (e == 0 || e == 4) ? k0 : k1;
            if (xi >= 0 && xi < 48) v += k * sc[xi];
        }
        dst[xo * 128 + tid] = v;
    }
}

// ---------------- fused blur Y+Z, fp16 out ----------------
// t1[n][z48][y48][xc] -> g_xh[n][z49][y49][xc], xc = x49*c128/4 = 1568 float4 lanes.
// Thread: fixed (n, yo, xc); streams z with a 5-deep register ring of y-blurred rows.
__global__ __launch_bounds__(256) void blurYZ() {
    int idx = blockIdx.x * 256 + threadIdx.x;
    const int total = NN * PP * 1568;      // (n, yo, xc)
    if (idx >= total) return;
    int xc = idx % 1568;
    int t = idx / 1568;
    int yo = t % PP;
    int n = t / PP;
    const float k0 = 1.f / 11.f, k1 = 3.f / 11.f;

    // valid y taps for this yo
    int yis[5]; float wy[5]; int nty = 0;
    #pragma unroll
    for (int e = 0; e < 5; e++) {
        int yi = yo + e - 3;
        if (yi >= 0 && yi < 48) { yis[nty] = yi; wy[nty] = (e == 0 || e == 4) ? k0 : k1; nty++; }
    }

    const float4* t1b = (const float4*)g_t1 + (size_t)n * 48 * 48 * 1568 + xc;
    uint2* dst = (uint2*)g_xh + ((size_t)n * PP * PP + yo) * 1568 + xc;   // +zo*PP*1568 per slice

    float4 r0, r1, r2, r3, r4;
    r0 = r1 = r2 = r3 = r4 = make_float4(0.f, 0.f, 0.f, 0.f);

    for (int zi = 0; zi < 50; zi++) {
        float4 ty = make_float4(0.f, 0.f, 0.f, 0.f);
        if (zi < 48) {
            for (int q = 0; q < nty; q++) {
                float4 d = t1b[(size_t)(zi * 48 + yis[q]) * 1568];
                float k = wy[q];
                ty.x += k * d.x; ty.y += k * d.y; ty.z += k * d.z; ty.w += k * d.w;
            }
        }
        r0 = r1; r1 = r2; r2 = r3; r3 = r4; r4 = ty;
        int zo = zi - 1;
        if (zo >= 0) {
            float4 o;
            o.x = k0 * (r0.x + r4.x) + k1 * (r1.x + r2.x + r3.x);
            o.y = k0 * (r0.y + r4.y) + k1 * (r1.y + r2.y + r3.y);
            o.z = k0 * (r0.z + r4.z) + k1 * (r1.z + r2.z + r3.z);
            o.w = k0 * (r0.w + r4.w) + k1 * (r1.w + r2.w + r3.w);
            __half h0 = __float2half(o.x), h1 = __float2half(o.y);
            __half h2 = __float2half(o.z), h3 = __float2half(o.w);
            uint2 pk;
            pk.x = (uint32_t)__half_as_ushort(h0) | ((uint32_t)__half_as_ushort(h1) << 16);
            pk.y = (uint32_t)__half_as_ushort(h2) | ((uint32_t)__half_as_ushort(h3) << 16);
            dst[(size_t)zo * PP * 1568] = pk;
        }
    }
}

// ---------------- GEMM via mma.sync fp16 (HMMA.16816), single term ----------------
// CTA: 128 oc x 64 spatial, 4 warps (2M x 2N), warp tile 64 x 32.
// Register-level fragment double-buffering: LDSM for k-step ks+1 issue under
// the 16 HMMAs of ks, breaking the per-kstep LDSM->HMMA dependency chain.
// 54 stages = 27 taps x 2 channel-halves (K=64). Stage = W 16KB + X 8KB = 24KB;
// 3 buffers = 72KB; cp.async depth-2 pipeline.
__global__ __launch_bounds__(128, 2) void gemm_k(const float* __restrict__ bias,
                                                 float* __restrict__ out) {
    extern __shared__ char smem[];
    __shared__ int s_soff[64];
    uint32_t sb = smem_u32(smem);
    int tid = threadIdx.x, wid = tid >> 5, lane = tid & 31;
    int stile = blockIdx.x, ocg = blockIdx.y;
    int wm = (wid & 1) * 64;      // M (oc) offset in CTA tile
    int wn = (wid >> 1) * 32;     // N (spatial) offset

    // spatial base offsets (in 256B rows of channel-last layout) — computed once
    if (tid < 64) {
        int s = stile * 64 + tid;
        int n = s / 13824; int r = s % 13824;
        int oz = r / 576, r2 = r % 576, oy = r2 / 24, ox = r2 % 24;
        s_soff[tid] = ((n * 49 + 2 * oz) * 49 + 2 * oy) * 49 + 2 * ox;
    }
    __syncthreads();

    // issue cp.async for one stage (tap, half) into buffer b
    auto load_stage = [&](int st, int b) {
        int tap = st >> 1, half = st & 1;
        int dz = tap / 9, dy = (tap / 3) % 3, dx = tap % 3;
        int dtap = dz * 2401 + dy * 49 + dx;
        uint32_t bufbase = sb + b * 24576;
        size_t adelta = (size_t)tap * 65536 + half * 128;       // bytes into g_w
        size_t bdelta = (size_t)dtap * 256 + half * 128;        // bytes into g_xh
        #pragma unroll
        for (int it = 0; it < 12; it++) {
            int i = tid + it * 128;
            int v = i & 7;
            const char* g;
            uint32_t daddr;
            if (i < 1024) {           // W tile: 128 rows x 128B
                int row = i >> 3;
                g = (const char*)g_w + adelta + (size_t)(ocg * 128 + row) * 256 + v * 16;
                daddr = bufbase + (uint32_t)(row * 128 + ((v ^ (row & 7)) * 16));
            } else {                  // X tile: 64 rows x 128B
                int row = (i >> 3) - 128;
                g = (const char*)g_xh + bdelta + (size_t)s_soff[row] * 256 + v * 16;
                daddr = bufbase + 16384 + (uint32_t)(row * 128 + ((v ^ (row & 7)) * 16));
            }
            cp_async16(daddr, g);
        }
        cp_commit();
    };

    float acc[4][4][4];
    #pragma unroll
    for (int i = 0; i < 4; i++)
        #pragma unroll
        for (int j = 0; j < 4; j++)
            #pragma unroll
            for (int q = 0; q < 4; q++) acc[i][j][q] = 0.f;

    // double-buffered fragments
    uint32_t aw[2][4][4];
    uint32_t bf[2][2][4];
    int arow = wm + (lane & 15);
    int brow0 = wn + (lane & 7) + ((lane >> 4) << 3);
    int asel = (lane >> 4);          // k-chunk select within ks
    int bsel = ((lane >> 3) & 1);

    load_stage(0, 0);
    load_stage(1, 1);

    for (int st = 0; st < 54; st++) {
        int b = st % 3;
        if (st >= 52) asm volatile("cp.async.wait_group 0;" ::: "memory");
        else          asm volatile("cp.async.wait_group 1;" ::: "memory");
        __syncthreads();   // all warps done with stage st-1 -> safe to refill its buffer
        if (st + 2 < 54) load_stage(st + 2, (st + 2) % 3);

        uint32_t bufbase = sb + b * 24576;
        uint32_t tW = bufbase, tX = bufbase + 16384;

        // preload fragments for ks = 0
        {
            int akb = asel, bkb = bsel;
            #pragma unroll
            for (int i = 0; i < 4; i++)
                ldsm_x4(aw[0][i], sw_addr(tW, arow + i * 16, akb));
            #pragma unroll
            for (int j2 = 0; j2 < 2; j2++)
                ldsm_x4(bf[0][j2], sw_addr(tX, brow0 + j2 * 16, bkb));
        }

        #pragma unroll
        for (int ks = 0; ks < 4; ks++) {
            int p = ks & 1;
            if (ks < 3) {   // prefetch ks+1 fragments under this ks's MMAs
                int akb = (ks + 1) * 2 + asel;
                int bkb = (ks + 1) * 2 + bsel;
                #pragma unroll
                for (int i = 0; i < 4; i++)
                    ldsm_x4(aw[p ^ 1][i], sw_addr(tW, arow + i * 16, akb));
                #pragma unroll
                for (int j2 = 0; j2 < 2; j2++)
                    ldsm_x4(bf[p ^ 1][j2], sw_addr(tX, brow0 + j2 * 16, bkb));
            }
            #pragma unroll
            for (int j2 = 0; j2 < 2; j2++) {
                #pragma unroll
                for (int i = 0; i < 4; i++) {
                    mma16816(acc[i][2 * j2],     aw[p][i], bf[p][j2]);      // n-lo
                    mma16816(acc[i][2 * j2 + 1], aw[p][i], bf[p][j2] + 2);  // n-hi
                }
            }
        }
    }

    // ---- epilogue: + bias, direct stores (pairs of consecutive spatial) ----
    #pragma unroll
    for (int i = 0; i < 4; i++) {
        int ocb = ocg * 128 + wm + i * 16 + (lane >> 2);
        float bv0 = bias[ocb], bv1 = bias[ocb + 8];
        #pragma unroll
        for (int j = 0; j < 4; j++) {
            int col = wn + j * 8 + (lane & 3) * 2;
            int s = stile * 64 + col;
            int nb = s / 13824, r2 = s % 13824;
            float2 v0 = make_float2(acc[i][j][0] + bv0, acc[i][j][1] + bv0);
            float2 v1 = make_float2(acc[i][j][2] + bv1, acc[i][j][3] + bv1);
            *(float2*)(out + ((size_t)(nb * OCN + ocb) * 13824 + r2)) = v0;
            *(float2*)(out + ((size_t)(nb * OCN + ocb + 8) * 13824 + r2)) = v1;
        }
    }
}

// ---------------- launch ----------------
extern "C" void kernel_launch(void* const* d_in, const int* in_sizes, int n_in,
                              void* d_out, int out_size) {
    const float* x    = (const float*)d_in[0];   // (2,128,48,48,48)
    const float* wgt  = (const float*)d_in[1];   // (256,128,3,3,3)
    const float* bias = (const float*)d_in[2];   // (256,)
    float* out = (float*)d_out;                  // (2,256,24,24,24)

    {
        int total = OCN * CC * 27;
        wprep<<<(total + 255) / 256, 256>>>(wgt);
    }
    {
        dim3 grid(48 * 48, NN);
        blurX<<<grid, 128>>>(x);
    }
    {
        int total = NN * PP * 1568;
        blurYZ<<<(total + 255) / 256, 256>>>();
    }
    {
        static int smem_set = 0;
        const int smem_bytes = 3 * 24576;   // 73728
        if (!smem_set) {
            cudaFuncSetAttribute(gemm_k, cudaFuncAttributeMaxDynamicSharedMemorySize, smem_bytes);
            smem_set = 1;
        }
        dim3 grid(STILES, 2);
        gemm_k<<<grid, 128, smem_bytes>>>(bias, out);
    }
}